// round 6
// baseline (speedup 1.0000x reference)
#include <cuda_runtime.h>
#include <cstdint>

#define MM 8192
#define KK 8192
#define DD 512

#define BM 128
#define BN 128
#define BK 16

// Scratch. NOTE: these symbols are referenced ONLY from device code.
// (Passing them as kernel arguments from host code yields a bogus pointer —
//  that was the R2-R5 failure.)
__device__ float g_agg[(size_t)MM * DD];    // tf32-rounded agg = adj @ x
__device__ float g_xtf[(size_t)KK * DD];    // tf32-rounded x
__device__ float g_wtf[(size_t)DD * DD];    // tf32-rounded W

__device__ __forceinline__ float f2tf(float x) {
    uint32_t r;
    asm("cvt.rna.tf32.f32 %0, %1;" : "=r"(r) : "f"(x));
    return __uint_as_float(r);
}

__device__ __forceinline__ void mma_tf32(float* d, const uint32_t* a, const uint32_t* b) {
    asm volatile(
        "mma.sync.aligned.m16n8k8.row.col.f32.tf32.tf32.f32 "
        "{%0,%1,%2,%3}, {%4,%5,%6,%7}, {%8,%9}, {%0,%1,%2,%3};\n"
        : "+f"(d[0]), "+f"(d[1]), "+f"(d[2]), "+f"(d[3])
        : "r"(a[0]), "r"(a[1]), "r"(a[2]), "r"(a[3]),
          "r"(b[0]), "r"(b[1]));
}

__device__ __forceinline__ void cp16(void* smem, const void* gmem) {
    uint32_t s = (uint32_t)__cvta_generic_to_shared(smem);
    asm volatile("cp.async.cg.shared.global [%0], [%1], 16;\n"
                 :: "r"(s), "l"(gmem) : "memory");
}
#define CP_COMMIT() asm volatile("cp.async.commit_group;\n" ::: "memory")
#define CP_WAIT0()  asm volatile("cp.async.wait_group 0;\n" ::: "memory")

// ---------------------------------------------------------------------------
// Pre-convert x and W to TF32 (RNA); writes device globals by symbol.
// ---------------------------------------------------------------------------
__global__ void convert_kernel(const float* __restrict__ x, const float* __restrict__ W) {
    const size_t XV = (size_t)KK * DD / 4;   // 1048576 float4
    const size_t WV = (size_t)DD * DD / 4;   // 65536 float4
    size_t i = (size_t)blockIdx.x * blockDim.x + threadIdx.x;
    if (i < XV) {
        float4 v = reinterpret_cast<const float4*>(x)[i];
        v.x = f2tf(v.x); v.y = f2tf(v.y); v.z = f2tf(v.z); v.w = f2tf(v.w);
        reinterpret_cast<float4*>(g_xtf)[i] = v;
    } else if (i < XV + WV) {
        size_t j = i - XV;
        float4 v = reinterpret_cast<const float4*>(W)[j];
        v.x = f2tf(v.x); v.y = f2tf(v.y); v.z = f2tf(v.z); v.w = f2tf(v.w);
        reinterpret_cast<float4*>(g_wtf)[j] = v;
    }
}

// ---------------------------------------------------------------------------
// GEMM1: g_agg = tf32( adj[M,K] @ g_xtf[K,D] )
// 2-stage cp.async pipeline, static smem. As [m][k] pitch 20, Bs [k][n] pitch 136.
// ---------------------------------------------------------------------------
__global__ void __launch_bounds__(256, 2)
gemm1_kernel(const float* __restrict__ A) {
    __shared__ float As[2][BM * 20];     // 2*2560 floats = 20480 B
    __shared__ float Bs[2][BK * 136];    // 2*2176 floats = 17408 B

    const int tid  = threadIdx.x;
    const int warp = tid >> 5;
    const int lane = tid & 31;
    const int g    = lane >> 2;
    const int tg   = lane & 3;
    const int wm   = warp & 3;
    const int wn   = warp >> 2;

    const int m0 = blockIdx.y * BM;
    const int n0 = blockIdx.x * BN;

    float acc[2][8][4];
    #pragma unroll
    for (int i = 0; i < 2; i++)
        #pragma unroll
        for (int j = 0; j < 8; j++)
            #pragma unroll
            for (int c = 0; c < 4; c++) acc[i][j][c] = 0.0f;

    // gmem->smem mappings
    const int ar = tid >> 2;   // 0..63  A row (stride 64)
    const int ac = tid & 3;    // 0..3   A float4 col
    const int br = tid >> 5;   // 0..7   B row (stride 8)
    const int bc = tid & 31;   // 0..31  B float4 col

    const float* Ab = &A[(size_t)(m0 + ar) * KK + ac * 4];
    const float* Bb = &g_xtf[(size_t)br * DD + n0 + bc * 4];   // device-side symbol ref

    // Prologue: stage 0
    #pragma unroll
    for (int i = 0; i < 2; i++)
        cp16(&As[0][(ar + i * 64) * 20 + ac * 4], Ab + (size_t)i * 64 * KK);
    #pragma unroll
    for (int i = 0; i < 2; i++)
        cp16(&Bs[0][(br + i * 8) * 136 + bc * 4], Bb + (size_t)i * 8 * DD);
    CP_COMMIT();

    const int NIT = KK / BK;   // 512
    for (int it = 0; it < NIT; it++) {
        CP_WAIT0();
        __syncthreads();   // stage (it&1) ready; all warps done with prev compute

        // Issue stage it+1 into the other buffer (overlaps with compute below)
        if (it + 1 < NIT) {
            const int nk = (it + 1) * BK;
            const int nb = (it + 1) & 1;
            #pragma unroll
            for (int i = 0; i < 2; i++)
                cp16(&As[nb][(ar + i * 64) * 20 + ac * 4], Ab + (size_t)i * 64 * KK + nk);
            #pragma unroll
            for (int i = 0; i < 2; i++)
                cp16(&Bs[nb][(br + i * 8) * 136 + bc * 4], Bb + (size_t)(nk + i * 8) * DD);
        }
        CP_COMMIT();

        // Compute on stage it&1
        const float* Ac = As[it & 1];
        const float* Bc = Bs[it & 1];
        #pragma unroll
        for (int ks = 0; ks < 2; ks++) {
            const int kk = ks * 8;
            uint32_t a[2][4];
            uint32_t b[8][2];
            #pragma unroll
            for (int i = 0; i < 2; i++) {
                int mb = wm * 32 + i * 16;
                a[i][0] = __float_as_uint(f2tf(Ac[(mb + g    ) * 20 + kk + tg    ]));
                a[i][1] = __float_as_uint(f2tf(Ac[(mb + g + 8) * 20 + kk + tg    ]));
                a[i][2] = __float_as_uint(f2tf(Ac[(mb + g    ) * 20 + kk + tg + 4]));
                a[i][3] = __float_as_uint(f2tf(Ac[(mb + g + 8) * 20 + kk + tg + 4]));
            }
            #pragma unroll
            for (int j = 0; j < 8; j++) {
                int nb2 = wn * 64 + j * 8 + g;
                b[j][0] = __float_as_uint(Bc[(kk + tg    ) * 136 + nb2]);
                b[j][1] = __float_as_uint(Bc[(kk + tg + 4) * 136 + nb2]);
            }
            #pragma unroll
            for (int i = 0; i < 2; i++)
                #pragma unroll
                for (int j = 0; j < 8; j++)
                    mma_tf32(acc[i][j], a[i], b[j]);
        }
    }

    // Epilogue: store agg pre-rounded to tf32 (gemm2 then needs no cvt)
    #pragma unroll
    for (int i = 0; i < 2; i++) {
        #pragma unroll
        for (int j = 0; j < 8; j++) {
            int m = m0 + wm * 32 + i * 16 + g;
            int n = n0 + wn * 64 + j * 8 + tg * 2;
            float2 v0 = make_float2(f2tf(acc[i][j][0]), f2tf(acc[i][j][1]));
            float2 v1 = make_float2(f2tf(acc[i][j][2]), f2tf(acc[i][j][3]));
            *reinterpret_cast<float2*>(&g_agg[(size_t)m * DD + n])       = v0;
            *reinterpret_cast<float2*>(&g_agg[(size_t)(m + 8) * DD + n]) = v1;
        }
    }
}

// ---------------------------------------------------------------------------
// GEMM2: out = relu( g_agg[M,D] @ g_wtf^T + bias )
// As [m][k] pitch 20, Ws [n][k] pitch 20 (straight copies).
// ---------------------------------------------------------------------------
__global__ void __launch_bounds__(256, 2)
gemm2_kernel(const float* __restrict__ bias, float* __restrict__ out) {
    __shared__ float As[2][BM * 20];
    __shared__ float Ws[2][BN * 20];

    const int tid  = threadIdx.x;
    const int warp = tid >> 5;
    const int lane = tid & 31;
    const int g    = lane >> 2;
    const int tg   = lane & 3;
    const int wm   = warp & 3;
    const int wn   = warp >> 2;

    const int m0 = blockIdx.y * BM;
    const int n0 = blockIdx.x * BN;

    float acc[2][8][4];
    #pragma unroll
    for (int i = 0; i < 2; i++)
        #pragma unroll
        for (int j = 0; j < 8; j++)
            #pragma unroll
            for (int c = 0; c < 4; c++) acc[i][j][c] = 0.0f;

    const int ar = tid >> 2;   // 0..63
    const int ac = tid & 3;    // 0..3

    const float* Ab = &g_agg[(size_t)(m0 + ar) * DD + ac * 4];
    const float* Wb = &g_wtf[(size_t)(n0 + ar) * DD + ac * 4];

    // Prologue: stage 0
    #pragma unroll
    for (int i = 0; i < 2; i++)
        cp16(&As[0][(ar + i * 64) * 20 + ac * 4], Ab + (size_t)i * 64 * DD);
    #pragma unroll
    for (int i = 0; i < 2; i++)
        cp16(&Ws[0][(ar + i * 64) * 20 + ac * 4], Wb + (size_t)i * 64 * DD);
    CP_COMMIT();

    const int NIT = DD / BK;   // 32
    for (int it = 0; it < NIT; it++) {
        CP_WAIT0();
        __syncthreads();

        if (it + 1 < NIT) {
            const int nk = (it + 1) * BK;
            const int nb = (it + 1) & 1;
            #pragma unroll
            for (int i = 0; i < 2; i++)
                cp16(&As[nb][(ar + i * 64) * 20 + ac * 4], Ab + (size_t)i * 64 * DD + nk);
            #pragma unroll
            for (int i = 0; i < 2; i++)
                cp16(&Ws[nb][(ar + i * 64) * 20 + ac * 4], Wb + (size_t)i * 64 * DD + nk);
        }
        CP_COMMIT();

        const float* Ac = As[it & 1];
        const float* Wc = Ws[it & 1];
        #pragma unroll
        for (int ks = 0; ks < 2; ks++) {
            const int kk = ks * 8;
            uint32_t a[2][4];
            uint32_t b[8][2];
            #pragma unroll
            for (int i = 0; i < 2; i++) {
                int mb = wm * 32 + i * 16;
                a[i][0] = __float_as_uint(Ac[(mb + g    ) * 20 + kk + tg    ]);
                a[i][1] = __float_as_uint(Ac[(mb + g + 8) * 20 + kk + tg    ]);
                a[i][2] = __float_as_uint(Ac[(mb + g    ) * 20 + kk + tg + 4]);
                a[i][3] = __float_as_uint(Ac[(mb + g + 8) * 20 + kk + tg + 4]);
            }
            #pragma unroll
            for (int j = 0; j < 8; j++) {
                int nb2 = wn * 64 + j * 8 + g;
                b[j][0] = __float_as_uint(Wc[nb2 * 20 + kk + tg    ]);
                b[j][1] = __float_as_uint(Wc[nb2 * 20 + kk + tg + 4]);
            }
            #pragma unroll
            for (int i = 0; i < 2; i++)
                #pragma unroll
                for (int j = 0; j < 8; j++)
                    mma_tf32(acc[i][j], a[i], b[j]);
        }
    }

    // Epilogue: bias + ReLU
    #pragma unroll
    for (int i = 0; i < 2; i++) {
        #pragma unroll
        for (int j = 0; j < 8; j++) {
            int m = m0 + wm * 32 + i * 16 + g;
            int n = n0 + wn * 64 + j * 8 + tg * 2;
            float b0 = bias[n], b1 = bias[n + 1];
            float2 v0 = make_float2(fmaxf(acc[i][j][0] + b0, 0.0f),
                                    fmaxf(acc[i][j][1] + b1, 0.0f));
            float2 v1 = make_float2(fmaxf(acc[i][j][2] + b0, 0.0f),
                                    fmaxf(acc[i][j][3] + b1, 0.0f));
            *reinterpret_cast<float2*>(&out[(size_t)m * DD + n])       = v0;
            *reinterpret_cast<float2*>(&out[(size_t)(m + 8) * DD + n]) = v1;
        }
    }
}

extern "C" void kernel_launch(void* const* d_in, const int* in_sizes, int n_in,
                              void* d_out, int out_size) {
    const float* x   = (const float*)d_in[0];  // [8192, 512]
    const float* adj = (const float*)d_in[1];  // [8192, 8192]
    const float* W   = (const float*)d_in[2];  // [512, 512]
    const float* b   = (const float*)d_in[3];  // [512]
    float* out = (float*)d_out;

    // Pre-convert x and W to tf32 (kernels touch globals by symbol only)
    const size_t nvec = (size_t)KK * DD / 4 + (size_t)DD * DD / 4;
    convert_kernel<<<(unsigned)((nvec + 255) / 256), 256>>>(x, W);

    dim3 grid(DD / BN, MM / BM);  // (4, 64) x-major: adj L2 reuse across N-tiles
    gemm1_kernel<<<grid, 256>>>(adj);
    gemm2_kernel<<<grid, 256>>>(b, out);
}

// round 14
// speedup vs baseline: 1.3967x; 1.3967x over previous
#include <cuda_runtime.h>
#include <cuda_fp16.h>
#include <cstdint>

#define MM 8192
#define KK 8192
#define DD 512

#define BM 128
#define BN 128
#define BK 32          // K-elements (halves) per tile
#define P  20          // smem row pitch in 32-bit words (= 40 halves = 80 B)

// Scratch — referenced ONLY from device code (host-passing these is the R2-R5 bug).
__device__ __half g_adjh[(size_t)MM * KK];   // fp16 adj          [m][k]  128 MB
__device__ __half g_xhT [(size_t)DD * KK];   // fp16 x^T          [n][k]    8 MB
__device__ __half g_wh  [(size_t)DD * DD];   // fp16 W            [n][k]  0.5 MB
__device__ __half g_aggh[(size_t)MM * DD];   // fp16 agg = adj@x  [m][k]    8 MB

__device__ __forceinline__ void mma_f16(float* d, const uint32_t* a, const uint32_t* b) {
    asm volatile(
        "mma.sync.aligned.m16n8k16.row.col.f32.f16.f16.f32 "
        "{%0,%1,%2,%3}, {%4,%5,%6,%7}, {%8,%9}, {%0,%1,%2,%3};\n"
        : "+f"(d[0]), "+f"(d[1]), "+f"(d[2]), "+f"(d[3])
        : "r"(a[0]), "r"(a[1]), "r"(a[2]), "r"(a[3]),
          "r"(b[0]), "r"(b[1]));
}

__device__ __forceinline__ void cp16(void* smem, const void* gmem) {
    uint32_t s = (uint32_t)__cvta_generic_to_shared(smem);
    asm volatile("cp.async.cg.shared.global [%0], [%1], 16;\n"
                 :: "r"(s), "l"(gmem) : "memory");
}
#define CP_COMMIT() asm volatile("cp.async.commit_group;\n" ::: "memory")
#define CP_WAIT0()  asm volatile("cp.async.wait_group 0;\n" ::: "memory")

// ---------------------------------------------------------------------------
// adj -> fp16 (straight).  16M threads x float4.
// ---------------------------------------------------------------------------
__global__ void conv_adj(const float* __restrict__ adj) {
    size_t i = (size_t)blockIdx.x * blockDim.x + threadIdx.x;   // float4 index
    float4 v = reinterpret_cast<const float4*>(adj)[i];
    __half2 h0 = __floats2half2_rn(v.x, v.y);
    __half2 h1 = __floats2half2_rn(v.z, v.w);
    uint2 w;
    w.x = *reinterpret_cast<uint32_t*>(&h0);
    w.y = *reinterpret_cast<uint32_t*>(&h1);
    reinterpret_cast<uint2*>(g_adjh)[i] = w;
}

// ---------------------------------------------------------------------------
// x[k][n] -> g_xhT[n][k] fp16.  32x32 smem-tiled transpose.
// ---------------------------------------------------------------------------
__global__ void conv_xT(const float* __restrict__ x) {
    __shared__ float t[32][33];
    const int k0 = blockIdx.x * 32;
    const int n0 = blockIdx.y * 32;
    const int tx = threadIdx.x & 31;
    const int ty = threadIdx.x >> 5;   // 0..7
    #pragma unroll
    for (int j = 0; j < 4; j++)
        t[ty + j * 8][tx] = x[(size_t)(k0 + ty + j * 8) * DD + n0 + tx];
    __syncthreads();
    #pragma unroll
    for (int j = 0; j < 4; j++)
        g_xhT[(size_t)(n0 + ty + j * 8) * KK + k0 + tx] = __float2half_rn(t[tx][ty + j * 8]);
}

// W[n][k] -> fp16 (straight)
__global__ void conv_w(const float* __restrict__ W) {
    size_t i = (size_t)blockIdx.x * blockDim.x + threadIdx.x;   // float4 index
    float4 v = reinterpret_cast<const float4*>(W)[i];
    __half2 h0 = __floats2half2_rn(v.x, v.y);
    __half2 h1 = __floats2half2_rn(v.z, v.w);
    uint2 w;
    w.x = *reinterpret_cast<uint32_t*>(&h0);
    w.y = *reinterpret_cast<uint32_t*>(&h1);
    reinterpret_cast<uint2*>(g_wh)[i] = w;
}

// ---------------------------------------------------------------------------
// GEMM1: g_aggh = fp16( adj_h[M,K] @ x_h[K,D] )
// CTA 128x128, BK=32 halves, 2-stage cp.async, warp tile 32x64 (m16n8k16).
// Smem [row][k] pitch 20 words; fragment half2 loads are conflict-free.
// ---------------------------------------------------------------------------
__global__ void __launch_bounds__(256, 2)
gemm1_h(void) {
    __shared__ uint32_t As[2][BM * P];   // 2*10240 B
    __shared__ uint32_t Bs[2][BN * P];   // 2*10240 B

    const int tid  = threadIdx.x;
    const int warp = tid >> 5;
    const int lane = tid & 31;
    const int g    = lane >> 2;
    const int tg   = lane & 3;
    const int wm   = warp & 3;
    const int wn   = warp >> 2;

    const int m0 = blockIdx.y * BM;
    const int n0 = blockIdx.x * BN;

    float acc[2][8][4];
    #pragma unroll
    for (int i = 0; i < 2; i++)
        #pragma unroll
        for (int j = 0; j < 8; j++)
            #pragma unroll
            for (int c = 0; c < 4; c++) acc[i][j][c] = 0.0f;

    // loaders: 128 rows x 64 B (4 x 16B chunks); 2 threads/row, 2 chunks each
    const int lr = tid >> 1;           // 0..127
    const int lc = (tid & 1) * 2;      // chunk base 0 or 2
    const __half* Ab = &g_adjh[(size_t)(m0 + lr) * KK + lc * 8];
    const __half* Bb = &g_xhT [(size_t)(n0 + lr) * KK + lc * 8];

    // Prologue
    #pragma unroll
    for (int j = 0; j < 2; j++) {
        cp16(&As[0][lr * P + (lc + j) * 4], Ab + j * 8);
        cp16(&Bs[0][lr * P + (lc + j) * 4], Bb + j * 8);
    }
    CP_COMMIT();

    const int NIT = KK / BK;   // 256
    for (int it = 0; it < NIT; it++) {
        CP_WAIT0();
        __syncthreads();

        if (it + 1 < NIT) {
            const int nk = (it + 1) * BK;
            const int nb = (it + 1) & 1;
            #pragma unroll
            for (int j = 0; j < 2; j++) {
                cp16(&As[nb][lr * P + (lc + j) * 4], Ab + nk + j * 8);
                cp16(&Bs[nb][lr * P + (lc + j) * 4], Bb + nk + j * 8);
            }
        }
        CP_COMMIT();

        const uint32_t* Ac = As[it & 1];
        const uint32_t* Bc = Bs[it & 1];
        #pragma unroll
        for (int ks = 0; ks < 2; ks++) {
            const int kw = ks * 8;   // word offset of this k16 slice
            uint32_t a[2][4];
            uint32_t b[8][2];
            #pragma unroll
            for (int i = 0; i < 2; i++) {
                int mb = wm * 32 + i * 16;
                a[i][0] = Ac[(mb + g    ) * P + kw + tg    ];
                a[i][1] = Ac[(mb + g + 8) * P + kw + tg    ];
                a[i][2] = Ac[(mb + g    ) * P + kw + tg + 4];
                a[i][3] = Ac[(mb + g + 8) * P + kw + tg + 4];
            }
            #pragma unroll
            for (int j = 0; j < 8; j++) {
                int nb2 = wn * 64 + j * 8 + g;
                b[j][0] = Bc[nb2 * P + kw + tg    ];
                b[j][1] = Bc[nb2 * P + kw + tg + 4];
            }
            #pragma unroll
            for (int i = 0; i < 2; i++)
                #pragma unroll
                for (int j = 0; j < 8; j++)
                    mma_f16(acc[i][j], a[i], b[j]);
        }
    }

    // Epilogue: agg -> fp16 (half2 stores)
    #pragma unroll
    for (int i = 0; i < 2; i++) {
        #pragma unroll
        for (int j = 0; j < 8; j++) {
            int m = m0 + wm * 32 + i * 16 + g;
            int n = n0 + wn * 64 + j * 8 + tg * 2;
            __half2 h0 = __floats2half2_rn(acc[i][j][0], acc[i][j][1]);
            __half2 h1 = __floats2half2_rn(acc[i][j][2], acc[i][j][3]);
            *reinterpret_cast<__half2*>(&g_aggh[(size_t)m * DD + n])       = h0;
            *reinterpret_cast<__half2*>(&g_aggh[(size_t)(m + 8) * DD + n]) = h1;
        }
    }
}

// ---------------------------------------------------------------------------
// GEMM2: out = relu( agg_h[M,D] @ W_h^T + bias ), fp32 accum/output.
// ---------------------------------------------------------------------------
__global__ void __launch_bounds__(256, 2)
gemm2_h(const float* __restrict__ bias, float* __restrict__ out) {
    __shared__ uint32_t As[2][BM * P];
    __shared__ uint32_t Ws[2][BN * P];

    const int tid  = threadIdx.x;
    const int warp = tid >> 5;
    const int lane = tid & 31;
    const int g    = lane >> 2;
    const int tg   = lane & 3;
    const int wm   = warp & 3;
    const int wn   = warp >> 2;

    const int m0 = blockIdx.y * BM;
    const int n0 = blockIdx.x * BN;

    float acc[2][8][4];
    #pragma unroll
    for (int i = 0; i < 2; i++)
        #pragma unroll
        for (int j = 0; j < 8; j++)
            #pragma unroll
            for (int c = 0; c < 4; c++) acc[i][j][c] = 0.0f;

    const int lr = tid >> 1;
    const int lc = (tid & 1) * 2;
    const __half* Ab = &g_aggh[(size_t)(m0 + lr) * DD + lc * 8];
    const __half* Wb = &g_wh  [(size_t)(n0 + lr) * DD + lc * 8];

    #pragma unroll
    for (int j = 0; j < 2; j++) {
        cp16(&As[0][lr * P + (lc + j) * 4], Ab + j * 8);
        cp16(&Ws[0][lr * P + (lc + j) * 4], Wb + j * 8);
    }
    CP_COMMIT();

    const int NIT = DD / BK;   // 16
    for (int it = 0; it < NIT; it++) {
        CP_WAIT0();
        __syncthreads();

        if (it + 1 < NIT) {
            const int nk = (it + 1) * BK;
            const int nb = (it + 1) & 1;
            #pragma unroll
            for (int j = 0; j < 2; j++) {
                cp16(&As[nb][lr * P + (lc + j) * 4], Ab + nk + j * 8);
                cp16(&Ws[nb][lr * P + (lc + j) * 4], Wb + nk + j * 8);
            }
        }
        CP_COMMIT();

        const uint32_t* Ac = As[it & 1];
        const uint32_t* Wc = Ws[it & 1];
        #pragma unroll
        for (int ks = 0; ks < 2; ks++) {
            const int kw = ks * 8;
            uint32_t a[2][4];
            uint32_t b[8][2];
            #pragma unroll
            for (int i = 0; i < 2; i++) {
                int mb = wm * 32 + i * 16;
                a[i][0] = Ac[(mb + g    ) * P + kw + tg    ];
                a[i][1] = Ac[(mb + g + 8) * P + kw + tg    ];
                a[i][2] = Ac[(mb + g    ) * P + kw + tg + 4];
                a[i][3] = Ac[(mb + g + 8) * P + kw + tg + 4];
            }
            #pragma unroll
            for (int j = 0; j < 8; j++) {
                int nb2 = wn * 64 + j * 8 + g;
                b[j][0] = Wc[nb2 * P + kw + tg    ];
                b[j][1] = Wc[nb2 * P + kw + tg + 4];
            }
            #pragma unroll
            for (int i = 0; i < 2; i++)
                #pragma unroll
                for (int j = 0; j < 8; j++)
                    mma_f16(acc[i][j], a[i], b[j]);
        }
    }

    // Epilogue: bias + ReLU (fp32)
    #pragma unroll
    for (int i = 0; i < 2; i++) {
        #pragma unroll
        for (int j = 0; j < 8; j++) {
            int m = m0 + wm * 32 + i * 16 + g;
            int n = n0 + wn * 64 + j * 8 + tg * 2;
            float b0 = bias[n], b1 = bias[n + 1];
            float2 v0 = make_float2(fmaxf(acc[i][j][0] + b0, 0.0f),
                                    fmaxf(acc[i][j][1] + b1, 0.0f));
            float2 v1 = make_float2(fmaxf(acc[i][j][2] + b0, 0.0f),
                                    fmaxf(acc[i][j][3] + b1, 0.0f));
            *reinterpret_cast<float2*>(&out[(size_t)m * DD + n])       = v0;
            *reinterpret_cast<float2*>(&out[(size_t)(m + 8) * DD + n]) = v1;
        }
    }
}

extern "C" void kernel_launch(void* const* d_in, const int* in_sizes, int n_in,
                              void* d_out, int out_size) {
    const float* x   = (const float*)d_in[0];  // [8192, 512]
    const float* adj = (const float*)d_in[1];  // [8192, 8192]
    const float* W   = (const float*)d_in[2];  // [512, 512]
    const float* b   = (const float*)d_in[3];  // [512]
    float* out = (float*)d_out;

    conv_adj<<<(unsigned)(((size_t)MM * KK / 4) / 256), 256>>>(adj);   // 65536 blocks
    conv_xT <<<dim3(KK / 32, DD / 32), 256>>>(x);                      // (256, 16)
    conv_w  <<<(DD * DD / 4) / 256, 256>>>(W);                         // 256 blocks

    dim3 grid(DD / BN, MM / BM);  // (4, 64) x-major: adj L2 reuse across N-tiles
    gemm1_h<<<grid, 256>>>();
    gemm2_h<<<grid, 256>>>(b, out);
}

// round 15
// speedup vs baseline: 1.4163x; 1.0140x over previous
#include <cuda_runtime.h>
#include <cuda_fp16.h>
#include <cstdint>

#define MM 8192
#define KK 8192
#define DD 512

#define BM 128
#define BN 128
#define BK 32          // K-elements (halves) per tile
#define P  20          // smem row pitch in 32-bit words (= 40 halves = 80 B)
#define NS 4           // gemm1 pipeline stages
#define STG_W (BM * P + BN * P)            // words per stage = 5120
#define G1_SMEM (NS * STG_W * 4)           // 81920 B dynamic smem

// Scratch — referenced ONLY from device code (host-passing these is the R2-R5 bug).
__device__ __half g_adjh[(size_t)MM * KK];   // fp16 adj          [m][k]  128 MB
__device__ __half g_xhT [(size_t)DD * KK];   // fp16 x^T          [n][k]    8 MB
__device__ __half g_wh  [(size_t)DD * DD];   // fp16 W            [n][k]  0.5 MB
__device__ __half g_aggh[(size_t)MM * DD];   // fp16 agg = adj@x  [m][k]    8 MB

__device__ __forceinline__ void mma_f16(float* d, const uint32_t* a, const uint32_t* b) {
    asm volatile(
        "mma.sync.aligned.m16n8k16.row.col.f32.f16.f16.f32 "
        "{%0,%1,%2,%3}, {%4,%5,%6,%7}, {%8,%9}, {%0,%1,%2,%3};\n"
        : "+f"(d[0]), "+f"(d[1]), "+f"(d[2]), "+f"(d[3])
        : "r"(a[0]), "r"(a[1]), "r"(a[2]), "r"(a[3]),
          "r"(b[0]), "r"(b[1]));
}

__device__ __forceinline__ void cp16(void* smem, const void* gmem) {
    uint32_t s = (uint32_t)__cvta_generic_to_shared(smem);
    asm volatile("cp.async.cg.shared.global [%0], [%1], 16;\n"
                 :: "r"(s), "l"(gmem) : "memory");
}
#define CP_COMMIT() asm volatile("cp.async.commit_group;\n" ::: "memory")
#define CP_WAIT(n)  asm volatile("cp.async.wait_group %0;\n" :: "n"(n) : "memory")

// ---------------------------------------------------------------------------
// adj -> fp16 (straight).
// ---------------------------------------------------------------------------
__global__ void conv_adj(const float* __restrict__ adj) {
    size_t i = (size_t)blockIdx.x * blockDim.x + threadIdx.x;   // float4 index
    float4 v = reinterpret_cast<const float4*>(adj)[i];
    __half2 h0 = __floats2half2_rn(v.x, v.y);
    __half2 h1 = __floats2half2_rn(v.z, v.w);
    uint2 w;
    w.x = *reinterpret_cast<uint32_t*>(&h0);
    w.y = *reinterpret_cast<uint32_t*>(&h1);
    reinterpret_cast<uint2*>(g_adjh)[i] = w;
}

// ---------------------------------------------------------------------------
// x[k][n] -> g_xhT[n][k] fp16.  32x32 smem-tiled transpose.
// ---------------------------------------------------------------------------
__global__ void conv_xT(const float* __restrict__ x) {
    __shared__ float t[32][33];
    const int k0 = blockIdx.x * 32;
    const int n0 = blockIdx.y * 32;
    const int tx = threadIdx.x & 31;
    const int ty = threadIdx.x >> 5;   // 0..7
    #pragma unroll
    for (int j = 0; j < 4; j++)
        t[ty + j * 8][tx] = x[(size_t)(k0 + ty + j * 8) * DD + n0 + tx];
    __syncthreads();
    #pragma unroll
    for (int j = 0; j < 4; j++)
        g_xhT[(size_t)(n0 + ty + j * 8) * KK + k0 + tx] = __float2half_rn(t[tx][ty + j * 8]);
}

// W[n][k] -> fp16 (straight)
__global__ void conv_w(const float* __restrict__ W) {
    size_t i = (size_t)blockIdx.x * blockDim.x + threadIdx.x;   // float4 index
    float4 v = reinterpret_cast<const float4*>(W)[i];
    __half2 h0 = __floats2half2_rn(v.x, v.y);
    __half2 h1 = __floats2half2_rn(v.z, v.w);
    uint2 w;
    w.x = *reinterpret_cast<uint32_t*>(&h0);
    w.y = *reinterpret_cast<uint32_t*>(&h1);
    reinterpret_cast<uint2*>(g_wh)[i] = w;
}

// ---------------------------------------------------------------------------
// GEMM1: g_aggh = fp16( adj_h[M,K] @ x_h[K,D] )
// CTA 128x128, BK=32, 4-stage cp.async pipeline (wait_group 2 => 2 loads in
// flight while computing), warp tile 32x64 (m16n8k16).
// ---------------------------------------------------------------------------
__global__ void __launch_bounds__(256, 2)
gemm1_h(void) {
    extern __shared__ uint32_t sm[];   // NS stages: [A: BM*P][B: BN*P]

    const int tid  = threadIdx.x;
    const int warp = tid >> 5;
    const int lane = tid & 31;
    const int g    = lane >> 2;
    const int tg   = lane & 3;
    const int wm   = warp & 3;
    const int wn   = warp >> 2;

    const int m0 = blockIdx.y * BM;
    const int n0 = blockIdx.x * BN;

    float acc[2][8][4];
    #pragma unroll
    for (int i = 0; i < 2; i++)
        #pragma unroll
        for (int j = 0; j < 8; j++)
            #pragma unroll
            for (int c = 0; c < 4; c++) acc[i][j][c] = 0.0f;

    // loaders: 128 rows x 64 B (4 x 16B chunks); 2 threads/row, 2 chunks each
    const int lr = tid >> 1;           // 0..127
    const int lc = (tid & 1) * 2;      // chunk base 0 or 2
    const __half* Ab = &g_adjh[(size_t)(m0 + lr) * KK + lc * 8];
    const __half* Bb = &g_xhT [(size_t)(n0 + lr) * KK + lc * 8];

    auto load_stage = [&](int s, int kt) {
        uint32_t* As = &sm[s * STG_W];
        uint32_t* Bs = As + BM * P;
        #pragma unroll
        for (int j = 0; j < 2; j++) {
            cp16(&As[lr * P + (lc + j) * 4], Ab + kt + j * 8);
            cp16(&Bs[lr * P + (lc + j) * 4], Bb + kt + j * 8);
        }
    };

    // Prologue: fill stages 0..2
    #pragma unroll
    for (int s = 0; s < NS - 1; s++) { load_stage(s, s * BK); CP_COMMIT(); }

    const int NIT = KK / BK;   // 256
    for (int it = 0; it < NIT; it++) {
        CP_WAIT(2);        // stage `it` landed; stages it+1, it+2 may be in flight
        __syncthreads();   // all warps past compute of it-1 -> buffer (it+3)&3 free

        if (it + 3 < NIT) load_stage((it + 3) & 3, (it + 3) * BK);
        CP_COMMIT();       // empty groups at tail keep numbering sound

        const uint32_t* Ac = &sm[(it & 3) * STG_W];
        const uint32_t* Bc = Ac + BM * P;
        #pragma unroll
        for (int ks = 0; ks < 2; ks++) {
            const int kw = ks * 8;   // word offset of this k16 slice
            uint32_t a[2][4];
            uint32_t b[8][2];
            #pragma unroll
            for (int i = 0; i < 2; i++) {
                int mb = wm * 32 + i * 16;
                a[i][0] = Ac[(mb + g    ) * P + kw + tg    ];
                a[i][1] = Ac[(mb + g + 8) * P + kw + tg    ];
                a[i][2] = Ac[(mb + g    ) * P + kw + tg + 4];
                a[i][3] = Ac[(mb + g + 8) * P + kw + tg + 4];
            }
            #pragma unroll
            for (int j = 0; j < 8; j++) {
                int nb2 = wn * 64 + j * 8 + g;
                b[j][0] = Bc[nb2 * P + kw + tg    ];
                b[j][1] = Bc[nb2 * P + kw + tg + 4];
            }
            #pragma unroll
            for (int i = 0; i < 2; i++)
                #pragma unroll
                for (int j = 0; j < 8; j++)
                    mma_f16(acc[i][j], a[i], b[j]);
        }
    }

    // Epilogue: agg -> fp16 (half2 stores)
    #pragma unroll
    for (int i = 0; i < 2; i++) {
        #pragma unroll
        for (int j = 0; j < 8; j++) {
            int m = m0 + wm * 32 + i * 16 + g;
            int n = n0 + wn * 64 + j * 8 + tg * 2;
            __half2 h0 = __floats2half2_rn(acc[i][j][0], acc[i][j][1]);
            __half2 h1 = __floats2half2_rn(acc[i][j][2], acc[i][j][3]);
            *reinterpret_cast<__half2*>(&g_aggh[(size_t)m * DD + n])       = h0;
            *reinterpret_cast<__half2*>(&g_aggh[(size_t)(m + 8) * DD + n]) = h1;
        }
    }
}

// ---------------------------------------------------------------------------
// GEMM2: out = relu( agg_h[M,D] @ W_h^T + bias ), fp32 accum/output.
// (2-stage static pipeline — only ~25us, unchanged from R14.)
// ---------------------------------------------------------------------------
__global__ void __launch_bounds__(256, 2)
gemm2_h(const float* __restrict__ bias, float* __restrict__ out) {
    __shared__ uint32_t As[2][BM * P];
    __shared__ uint32_t Ws[2][BN * P];

    const int tid  = threadIdx.x;
    const int warp = tid >> 5;
    const int lane = tid & 31;
    const int g    = lane >> 2;
    const int tg   = lane & 3;
    const int wm   = warp & 3;
    const int wn   = warp >> 2;

    const int m0 = blockIdx.y * BM;
    const int n0 = blockIdx.x * BN;

    float acc[2][8][4];
    #pragma unroll
    for (int i = 0; i < 2; i++)
        #pragma unroll
        for (int j = 0; j < 8; j++)
            #pragma unroll
            for (int c = 0; c < 4; c++) acc[i][j][c] = 0.0f;

    const int lr = tid >> 1;
    const int lc = (tid & 1) * 2;
    const __half* Ab = &g_aggh[(size_t)(m0 + lr) * DD + lc * 8];
    const __half* Wb = &g_wh  [(size_t)(n0 + lr) * DD + lc * 8];

    #pragma unroll
    for (int j = 0; j < 2; j++) {
        cp16(&As[0][lr * P + (lc + j) * 4], Ab + j * 8);
        cp16(&Ws[0][lr * P + (lc + j) * 4], Wb + j * 8);
    }
    CP_COMMIT();

    const int NIT = DD / BK;   // 16
    for (int it = 0; it < NIT; it++) {
        CP_WAIT(0);
        __syncthreads();

        if (it + 1 < NIT) {
            const int nk = (it + 1) * BK;
            const int nb = (it + 1) & 1;
            #pragma unroll
            for (int j = 0; j < 2; j++) {
                cp16(&As[nb][lr * P + (lc + j) * 4], Ab + nk + j * 8);
                cp16(&Ws[nb][lr * P + (lc + j) * 4], Wb + nk + j * 8);
            }
        }
        CP_COMMIT();

        const uint32_t* Ac = As[it & 1];
        const uint32_t* Wc = Ws[it & 1];
        #pragma unroll
        for (int ks = 0; ks < 2; ks++) {
            const int kw = ks * 8;
            uint32_t a[2][4];
            uint32_t b[8][2];
            #pragma unroll
            for (int i = 0; i < 2; i++) {
                int mb = wm * 32 + i * 16;
                a[i][0] = Ac[(mb + g    ) * P + kw + tg    ];
                a[i][1] = Ac[(mb + g + 8) * P + kw + tg    ];
                a[i][2] = Ac[(mb + g    ) * P + kw + tg + 4];
                a[i][3] = Ac[(mb + g + 8) * P + kw + tg + 4];
            }
            #pragma unroll
            for (int j = 0; j < 8; j++) {
                int nb2 = wn * 64 + j * 8 + g;
                b[j][0] = Wc[nb2 * P + kw + tg    ];
                b[j][1] = Wc[nb2 * P + kw + tg + 4];
            }
            #pragma unroll
            for (int i = 0; i < 2; i++)
                #pragma unroll
                for (int j = 0; j < 8; j++)
                    mma_f16(acc[i][j], a[i], b[j]);
        }
    }

    #pragma unroll
    for (int i = 0; i < 2; i++) {
        #pragma unroll
        for (int j = 0; j < 8; j++) {
            int m = m0 + wm * 32 + i * 16 + g;
            int n = n0 + wn * 64 + j * 8 + tg * 2;
            float b0 = bias[n], b1 = bias[n + 1];
            float2 v0 = make_float2(fmaxf(acc[i][j][0] + b0, 0.0f),
                                    fmaxf(acc[i][j][1] + b1, 0.0f));
            float2 v1 = make_float2(fmaxf(acc[i][j][2] + b0, 0.0f),
                                    fmaxf(acc[i][j][3] + b1, 0.0f));
            *reinterpret_cast<float2*>(&out[(size_t)m * DD + n])       = v0;
            *reinterpret_cast<float2*>(&out[(size_t)(m + 8) * DD + n]) = v1;
        }
    }
}

extern "C" void kernel_launch(void* const* d_in, const int* in_sizes, int n_in,
                              void* d_out, int out_size) {
    const float* x   = (const float*)d_in[0];  // [8192, 512]
    const float* adj = (const float*)d_in[1];  // [8192, 8192]
    const float* W   = (const float*)d_in[2];  // [512, 512]
    const float* b   = (const float*)d_in[3];  // [512]
    float* out = (float*)d_out;

    // Opt-in >48KB dynamic smem — only outside graph capture (persists).
    cudaStreamCaptureStatus cap = cudaStreamCaptureStatusNone;
    cudaStreamIsCapturing(0, &cap);
    if (cap == cudaStreamCaptureStatusNone) {
        cudaFuncSetAttribute(gemm1_h, cudaFuncAttributeMaxDynamicSharedMemorySize, G1_SMEM);
    }

    conv_adj<<<(unsigned)(((size_t)MM * KK / 4) / 256), 256>>>(adj);
    conv_xT <<<dim3(KK / 32, DD / 32), 256>>>(x);
    conv_w  <<<(DD * DD / 4) / 256, 256>>>(W);

    dim3 grid(DD / BN, MM / BM);  // (4, 64) x-major: adj L2 reuse across N-tiles
    gemm1_h<<<grid, 256, G1_SMEM>>>();
    gemm2_h<<<grid, 256>>>(b, out);
}

// round 16
// speedup vs baseline: 1.5652x; 1.1052x over previous
#include <cuda_runtime.h>
#include <cuda_fp16.h>
#include <cstdint>

#define MM 8192
#define KK 8192
#define DD 512

#define BM 128
#define BN 128
#define BK 32          // K-elements (halves) per tile
#define P  20          // smem row pitch in 32-bit words (= 40 halves = 80 B)
#define NS 4           // gemm1 pipeline stages
#define STG_W (BM * P + BN * P)            // words per stage = 5120
#define G1_SMEM (NS * STG_W * 4)           // 81920 B dynamic smem

// Scratch — referenced ONLY from device code (host-passing these is the R2-R5 bug).
__device__ __half g_adjh[(size_t)MM * KK];   // fp16 adj          [m][k]  128 MB
__device__ __half g_xhT [(size_t)DD * KK];   // fp16 x^T          [n][k]    8 MB
__device__ __half g_wh  [(size_t)DD * DD];   // fp16 W            [n][k]  0.5 MB
__device__ __half g_aggh[(size_t)MM * DD];   // fp16 agg = adj@x  [m][k]    8 MB

__device__ __forceinline__ void mma_f16(float* d, const uint32_t* a, const uint32_t* b) {
    asm volatile(
        "mma.sync.aligned.m16n8k16.row.col.f32.f16.f16.f32 "
        "{%0,%1,%2,%3}, {%4,%5,%6,%7}, {%8,%9}, {%0,%1,%2,%3};\n"
        : "+f"(d[0]), "+f"(d[1]), "+f"(d[2]), "+f"(d[3])
        : "r"(a[0]), "r"(a[1]), "r"(a[2]), "r"(a[3]),
          "r"(b[0]), "r"(b[1]));
}

__device__ __forceinline__ void ldsm_x4(uint32_t* r, uint32_t saddr) {
    asm volatile("ldmatrix.sync.aligned.m8n8.x4.shared.b16 {%0,%1,%2,%3}, [%4];"
                 : "=r"(r[0]), "=r"(r[1]), "=r"(r[2]), "=r"(r[3])
                 : "r"(saddr));
}

__device__ __forceinline__ void cp16(void* smem, const void* gmem) {
    uint32_t s = (uint32_t)__cvta_generic_to_shared(smem);
    asm volatile("cp.async.cg.shared.global [%0], [%1], 16;\n"
                 :: "r"(s), "l"(gmem) : "memory");
}
#define CP_COMMIT() asm volatile("cp.async.commit_group;\n" ::: "memory")
#define CP_WAIT(n)  asm volatile("cp.async.wait_group %0;\n" :: "n"(n) : "memory")

// ---------------------------------------------------------------------------
// Converters
// ---------------------------------------------------------------------------
__global__ void conv_adj(const float* __restrict__ adj) {
    size_t i = (size_t)blockIdx.x * blockDim.x + threadIdx.x;   // float4 index
    float4 v = reinterpret_cast<const float4*>(adj)[i];
    __half2 h0 = __floats2half2_rn(v.x, v.y);
    __half2 h1 = __floats2half2_rn(v.z, v.w);
    uint2 w;
    w.x = *reinterpret_cast<uint32_t*>(&h0);
    w.y = *reinterpret_cast<uint32_t*>(&h1);
    reinterpret_cast<uint2*>(g_adjh)[i] = w;
}

__global__ void conv_xT(const float* __restrict__ x) {
    __shared__ float t[32][33];
    const int k0 = blockIdx.x * 32;
    const int n0 = blockIdx.y * 32;
    const int tx = threadIdx.x & 31;
    const int ty = threadIdx.x >> 5;   // 0..7
    #pragma unroll
    for (int j = 0; j < 4; j++)
        t[ty + j * 8][tx] = x[(size_t)(k0 + ty + j * 8) * DD + n0 + tx];
    __syncthreads();
    #pragma unroll
    for (int j = 0; j < 4; j++)
        g_xhT[(size_t)(n0 + ty + j * 8) * KK + k0 + tx] = __float2half_rn(t[tx][ty + j * 8]);
}

__global__ void conv_w(const float* __restrict__ W) {
    size_t i = (size_t)blockIdx.x * blockDim.x + threadIdx.x;   // float4 index
    float4 v = reinterpret_cast<const float4*>(W)[i];
    __half2 h0 = __floats2half2_rn(v.x, v.y);
    __half2 h1 = __floats2half2_rn(v.z, v.w);
    uint2 w;
    w.x = *reinterpret_cast<uint32_t*>(&h0);
    w.y = *reinterpret_cast<uint32_t*>(&h1);
    reinterpret_cast<uint2*>(g_wh)[i] = w;
}

// ---------------------------------------------------------------------------
// GEMM1: g_aggh = fp16( adj_h[M,K] @ x_h[K,D] )
// CTA 128x128, BK=32, 4-stage cp.async, ldmatrix.x4 fragment loads.
// ---------------------------------------------------------------------------
__global__ void __launch_bounds__(256, 2)
gemm1_h(void) {
    extern __shared__ uint32_t sm[];   // NS stages: [A: BM*P][B: BN*P]
    const uint32_t smb = (uint32_t)__cvta_generic_to_shared(sm);

    const int tid  = threadIdx.x;
    const int warp = tid >> 5;
    const int lane = tid & 31;
    const int g    = lane >> 2;
    const int tg   = lane & 3;
    const int wm   = warp & 3;
    const int wn   = warp >> 2;

    const int m0 = blockIdx.y * BM;
    const int n0 = blockIdx.x * BN;

    float acc[2][8][4];
    #pragma unroll
    for (int i = 0; i < 2; i++)
        #pragma unroll
        for (int j = 0; j < 8; j++)
            #pragma unroll
            for (int c = 0; c < 4; c++) acc[i][j][c] = 0.0f;

    // ldmatrix lane-dependent offsets (bytes). Row = +8 for lane-octet 1/3,
    // col word +4 (k8-15) for octets 2/3.
    const int lrow = ((lane >> 3) & 1) * 8 + (lane & 7);
    const int lcol = (lane >> 4) * 4;
    uint32_t a_off[2], b_off[4];
    #pragma unroll
    for (int i = 0; i < 2; i++)
        a_off[i] = (uint32_t)(((wm * 32 + i * 16 + lrow) * P + lcol) * 4);
    #pragma unroll
    for (int jp = 0; jp < 4; jp++)
        b_off[jp] = (uint32_t)((BM * P + (wn * 64 + jp * 16 + lrow) * P + lcol) * 4);

    // gmem->smem loaders: 128 rows x 64 B (4 x 16B chunks); 2 threads/row
    const int lr = tid >> 1;           // 0..127
    const int lc = (tid & 1) * 2;      // chunk base 0 or 2
    const __half* Ab = &g_adjh[(size_t)(m0 + lr) * KK + lc * 8];
    const __half* Bb = &g_xhT [(size_t)(n0 + lr) * KK + lc * 8];

    auto load_stage = [&](int s, int kt) {
        uint32_t* As = &sm[s * STG_W];
        uint32_t* Bs = As + BM * P;
        #pragma unroll
        for (int j = 0; j < 2; j++) {
            cp16(&As[lr * P + (lc + j) * 4], Ab + kt + j * 8);
            cp16(&Bs[lr * P + (lc + j) * 4], Bb + kt + j * 8);
        }
    };

    // Prologue: fill stages 0..2
    #pragma unroll
    for (int s = 0; s < NS - 1; s++) { load_stage(s, s * BK); CP_COMMIT(); }

    const int NIT = KK / BK;   // 256
    for (int it = 0; it < NIT; it++) {
        CP_WAIT(2);
        __syncthreads();

        if (it + 3 < NIT) load_stage((it + 3) & 3, (it + 3) * BK);
        CP_COMMIT();

        const uint32_t stage = smb + (uint32_t)((it & 3) * STG_W * 4);
        #pragma unroll
        for (int ks = 0; ks < 2; ks++) {
            const uint32_t kb = stage + ks * 32;   // k16 slice = 8 words = 32 B
            uint32_t a[2][4];
            uint32_t b[8][2];
            ldsm_x4(a[0], kb + a_off[0]);
            ldsm_x4(a[1], kb + a_off[1]);
            #pragma unroll
            for (int jp = 0; jp < 4; jp++) {
                uint32_t bb[4];
                ldsm_x4(bb, kb + b_off[jp]);
                b[2 * jp][0]     = bb[0];
                b[2 * jp + 1][0] = bb[1];
                b[2 * jp][1]     = bb[2];
                b[2 * jp + 1][1] = bb[3];
            }
            #pragma unroll
            for (int i = 0; i < 2; i++)
                #pragma unroll
                for (int j = 0; j < 8; j++)
                    mma_f16(acc[i][j], a[i], b[j]);
        }
    }

    // Epilogue: agg -> fp16 (half2 stores)
    #pragma unroll
    for (int i = 0; i < 2; i++) {
        #pragma unroll
        for (int j = 0; j < 8; j++) {
            int m = m0 + wm * 32 + i * 16 + g;
            int n = n0 + wn * 64 + j * 8 + tg * 2;
            __half2 h0 = __floats2half2_rn(acc[i][j][0], acc[i][j][1]);
            __half2 h1 = __floats2half2_rn(acc[i][j][2], acc[i][j][3]);
            *reinterpret_cast<__half2*>(&g_aggh[(size_t)m * DD + n])       = h0;
            *reinterpret_cast<__half2*>(&g_aggh[(size_t)(m + 8) * DD + n]) = h1;
        }
    }
}

// ---------------------------------------------------------------------------
// GEMM2: out = relu( agg_h[M,D] @ W_h^T + bias ), fp32 accum/output.
// ---------------------------------------------------------------------------
__global__ void __launch_bounds__(256, 2)
gemm2_h(const float* __restrict__ bias, float* __restrict__ out) {
    __shared__ uint32_t As[2][BM * P];
    __shared__ uint32_t Ws[2][BN * P];
    const uint32_t smbA = (uint32_t)__cvta_generic_to_shared(&As[0][0]);
    const uint32_t smbW = (uint32_t)__cvta_generic_to_shared(&Ws[0][0]);

    const int tid  = threadIdx.x;
    const int warp = tid >> 5;
    const int lane = tid & 31;
    const int g    = lane >> 2;
    const int tg   = lane & 3;
    const int wm   = warp & 3;
    const int wn   = warp >> 2;

    const int m0 = blockIdx.y * BM;
    const int n0 = blockIdx.x * BN;

    float acc[2][8][4];
    #pragma unroll
    for (int i = 0; i < 2; i++)
        #pragma unroll
        for (int j = 0; j < 8; j++)
            #pragma unroll
            for (int c = 0; c < 4; c++) acc[i][j][c] = 0.0f;

    const int lrow = ((lane >> 3) & 1) * 8 + (lane & 7);
    const int lcol = (lane >> 4) * 4;
    uint32_t a_off[2], b_off[4];
    #pragma unroll
    for (int i = 0; i < 2; i++)
        a_off[i] = (uint32_t)(((wm * 32 + i * 16 + lrow) * P + lcol) * 4);
    #pragma unroll
    for (int jp = 0; jp < 4; jp++)
        b_off[jp] = (uint32_t)(((wn * 64 + jp * 16 + lrow) * P + lcol) * 4);

    const int lr = tid >> 1;
    const int lc = (tid & 1) * 2;
    const __half* Ab = &g_aggh[(size_t)(m0 + lr) * DD + lc * 8];
    const __half* Wb = &g_wh  [(size_t)(n0 + lr) * DD + lc * 8];

    #pragma unroll
    for (int j = 0; j < 2; j++) {
        cp16(&As[0][lr * P + (lc + j) * 4], Ab + j * 8);
        cp16(&Ws[0][lr * P + (lc + j) * 4], Wb + j * 8);
    }
    CP_COMMIT();

    const int NIT = DD / BK;   // 16
    for (int it = 0; it < NIT; it++) {
        CP_WAIT(0);
        __syncthreads();

        if (it + 1 < NIT) {
            const int nk = (it + 1) * BK;
            const int nb = (it + 1) & 1;
            #pragma unroll
            for (int j = 0; j < 2; j++) {
                cp16(&As[nb][lr * P + (lc + j) * 4], Ab + nk + j * 8);
                cp16(&Ws[nb][lr * P + (lc + j) * 4], Wb + nk + j * 8);
            }
        }
        CP_COMMIT();

        const uint32_t sA = smbA + (uint32_t)((it & 1) * BM * P * 4);
        const uint32_t sW = smbW + (uint32_t)((it & 1) * BN * P * 4);
        #pragma unroll
        for (int ks = 0; ks < 2; ks++) {
            const uint32_t kb = ks * 32;
            uint32_t a[2][4];
            uint32_t b[8][2];
            ldsm_x4(a[0], sA + kb + a_off[0]);
            ldsm_x4(a[1], sA + kb + a_off[1]);
            #pragma unroll
            for (int jp = 0; jp < 4; jp++) {
                uint32_t bb[4];
                ldsm_x4(bb, sW + kb + b_off[jp]);
                b[2 * jp][0]     = bb[0];
                b[2 * jp + 1][0] = bb[1];
                b[2 * jp][1]     = bb[2];
                b[2 * jp + 1][1] = bb[3];
            }
            #pragma unroll
            for (int i = 0; i < 2; i++)
                #pragma unroll
                for (int j = 0; j < 8; j++)
                    mma_f16(acc[i][j], a[i], b[j]);
        }
    }

    #pragma unroll
    for (int i = 0; i < 2; i++) {
        #pragma unroll
        for (int j = 0; j < 8; j++) {
            int m = m0 + wm * 32 + i * 16 + g;
            int n = n0 + wn * 64 + j * 8 + tg * 2;
            float b0 = bias[n], b1 = bias[n + 1];
            float2 v0 = make_float2(fmaxf(acc[i][j][0] + b0, 0.0f),
                                    fmaxf(acc[i][j][1] + b1, 0.0f));
            float2 v1 = make_float2(fmaxf(acc[i][j][2] + b0, 0.0f),
                                    fmaxf(acc[i][j][3] + b1, 0.0f));
            *reinterpret_cast<float2*>(&out[(size_t)m * DD + n])       = v0;
            *reinterpret_cast<float2*>(&out[(size_t)(m + 8) * DD + n]) = v1;
        }
    }
}

extern "C" void kernel_launch(void* const* d_in, const int* in_sizes, int n_in,
                              void* d_out, int out_size) {
    const float* x   = (const float*)d_in[0];  // [8192, 512]
    const float* adj = (const float*)d_in[1];  // [8192, 8192]
    const float* W   = (const float*)d_in[2];  // [512, 512]
    const float* b   = (const float*)d_in[3];  // [512]
    float* out = (float*)d_out;

    cudaStreamCaptureStatus cap = cudaStreamCaptureStatusNone;
    cudaStreamIsCapturing(0, &cap);
    if (cap == cudaStreamCaptureStatusNone) {
        cudaFuncSetAttribute(gemm1_h, cudaFuncAttributeMaxDynamicSharedMemorySize, G1_SMEM);
    }

    conv_adj<<<(unsigned)(((size_t)MM * KK / 4) / 256), 256>>>(adj);
    conv_xT <<<dim3(KK / 32, DD / 32), 256>>>(x);
    conv_w  <<<(DD * DD / 4) / 256, 256>>>(W);

    dim3 grid(DD / BN, MM / BM);  // (4, 64) x-major: adj L2 reuse across N-tiles
    gemm1_h<<<grid, 256, G1_SMEM>>>();
    gemm2_h<<<grid, 256>>>(b, out);
}